// round 5
// baseline (speedup 1.0000x reference)
#include <cuda_runtime.h>
#include <cstdint>

// out[i] = one_hot(argmax_j( b[j] + sum_k x[i,k]*W[k,j] ), 64)
//
// R5: persistent kernel, 1 block/SM, 256 threads, 256-row tiles,
// double-buffered x staging via cp.async (prefetch next tile during compute).
// Geometry (same as the passing R3 kernel):
//   g = t>>3 in [0,32): rows 8g..8g+7 of the tile
//   a = t&7: cols {4a..4a+3} U {32+4a..32+4a+3}
//   acc = 8 rows x 8 cols packed f32x2 = 64 regs.
// One __syncthreads per tile; labels distributed by 8-lane shuffle reduce;
// each thread stores its own rows (two 128B chunks per row per 8-thread group).
// Numerics: per column b-init + ascending-k fp32 fma.rn.f32x2 chain ==
// bit-identical to rounds 1-3 (rel_err = 1 flipped row, zero margin).

#define DIMS 64
#define TPB 256
#define TROWS 256

// smem floats: Ws[4096] | bs[64] | xs[2][16384]
#define SMEM_FLOATS (4096 + 64 + 2 * 16384)
#define SMEM_BYTES (SMEM_FLOATS * 4)   // 147,712 B

__device__ __forceinline__ unsigned long long fma2(unsigned long long a,
                                                   unsigned long long b,
                                                   unsigned long long c) {
    unsigned long long d;
    asm("fma.rn.f32x2 %0, %1, %2, %3;" : "=l"(d) : "l"(a), "l"(b), "l"(c));
    return d;
}
__device__ __forceinline__ unsigned long long dup2(float x) {
    unsigned long long d;
    asm("mov.b64 %0, {%1, %1};" : "=l"(d) : "f"(x));
    return d;
}
__device__ __forceinline__ void unpack2(unsigned long long v, float& lo, float& hi) {
    asm("mov.b64 {%0, %1}, %2;" : "=f"(lo), "=f"(hi) : "l"(v));
}
__device__ __forceinline__ void cp16(uint32_t dst, const void* src) {
    asm volatile("cp.async.cg.shared.global [%0], [%1], 16;" :: "r"(dst), "l"(src));
}

__global__ void __launch_bounds__(TPB, 1)
onehot_argmax_kernel(const float* __restrict__ x,
                     const float* __restrict__ W,
                     const float* __restrict__ b,
                     float* __restrict__ out,
                     int ntiles) {
    extern __shared__ float smem[];
    float* Ws = smem;                 // [64][64] k-major
    float* bs = Ws + 4096;            // [64]
    float* xs = bs + 64;              // 2 x (256 rows * 64 f), swizzled

    const int t = threadIdx.x;
    const int g = t >> 3;             // row group 0..31, rows 8g..8g+7
    const int a = t & 7;              // column selector
    const int stride = gridDim.x;

    const uint32_t s_ws = (uint32_t)__cvta_generic_to_shared(Ws);
    const uint32_t s_bs = (uint32_t)__cvta_generic_to_shared(bs);
    const uint32_t s_xs = (uint32_t)__cvta_generic_to_shared(xs);

    if (blockIdx.x >= ntiles) return;  // safety (not hit at B=2^21)

    // ---- prologue: stage W, b, and tile0 x into buffer 0 ----
    {
        const float4* W4 = (const float4*)W;
#pragma unroll
        for (int i = 0; i < 4; i++)
            cp16(s_ws + (t + i * TPB) * 16, W4 + t + i * TPB);
        if (t < 16) cp16(s_bs + t * 16, ((const float4*)b) + t);

        const float4* xg = (const float4*)x + (long long)blockIdx.x * (TROWS * (DIMS / 4));
#pragma unroll
        for (int it = 0; it < 16; it++) {
            int f = t + it * TPB;             // 0..4095
            int row = f >> 4, q = f & 15;
            int off = row * 64 + ((4 * q) ^ (row & 0x1C));
            cp16(s_xs + off * 4, xg + f);
        }
        asm volatile("cp.async.commit_group;" ::: "memory");
    }

    const int swb = (g & 3) << 3;     // swizzle base for this thread's rows
    int buf = 0;

    for (int tile = blockIdx.x; tile < ntiles; tile += stride) {
        asm volatile("cp.async.wait_group 0;" ::: "memory");
        __syncthreads();   // buf data visible; prior compute on buf^1 finished

        // ---- prefetch next tile into buf^1 (overlaps compute below) ----
        {
            int nt = tile + stride;
            if (nt >= ntiles) nt = tile;      // harmless in-bounds duplicate
            const float4* xg = (const float4*)x + (long long)nt * (TROWS * (DIMS / 4));
            const uint32_t s_dst = s_xs + (uint32_t)(buf ^ 1) * (16384u * 4u);
#pragma unroll
            for (int it = 0; it < 16; it++) {
                int f = t + it * TPB;
                int row = f >> 4, q = f & 15;
                int off = row * 64 + ((4 * q) ^ (row & 0x1C));
                cp16(s_dst + off * 4, xg + f);
            }
            asm volatile("cp.async.commit_group;" ::: "memory");
        }

        // ---- init acc with b ----
        unsigned long long acc[8][4];
        {
            ulonglong2 b0 = *(const ulonglong2*)(bs + 4 * a);
            ulonglong2 b1 = *(const ulonglong2*)(bs + 32 + 4 * a);
#pragma unroll
            for (int i = 0; i < 8; i++) {
                acc[i][0] = b0.x; acc[i][1] = b0.y;
                acc[i][2] = b1.x; acc[i][3] = b1.y;
            }
        }

        const float* xbase = xs + buf * 16384 + (g << 9);  // 8g * 64

        // ---- mainloop: 16 k-quads, 64 k total ----
#pragma unroll 2
        for (int kq = 0; kq < 16; kq++) {
            const int e0 = (4 * kq) ^ swb;
            const int e4 = (4 * kq) ^ (swb + 4);
            float4 xr[8];
#pragma unroll
            for (int i = 0; i < 8; i++)
                xr[i] = *(const float4*)(xbase + (i << 6) + ((i & 4) ? e4 : e0));
#pragma unroll
            for (int dk = 0; dk < 4; dk++) {
                const int k = 4 * kq + dk;
                ulonglong2 w0 = *(const ulonglong2*)(Ws + (k << 6) + 4 * a);
                ulonglong2 w1 = *(const ulonglong2*)(Ws + (k << 6) + 32 + 4 * a);
#pragma unroll
                for (int i = 0; i < 8; i++) {
                    float xk = (dk == 0) ? xr[i].x : (dk == 1) ? xr[i].y
                             : (dk == 2) ? xr[i].z : xr[i].w;
                    unsigned long long x2 = dup2(xk);
                    acc[i][0] = fma2(x2, w0.x, acc[i][0]);
                    acc[i][1] = fma2(x2, w0.y, acc[i][1]);
                    acc[i][2] = fma2(x2, w1.x, acc[i][2]);
                    acc[i][3] = fma2(x2, w1.y, acc[i][3]);
                }
            }
        }

        // ---- per-thread argmax over its 8 cols (ascending j, strict >) ----
        float bv[8];
        int bj[8];
#pragma unroll
        for (int i = 0; i < 8; i++) { bv[i] = __int_as_float(0xff800000); bj[i] = 0; }
#pragma unroll
        for (int c = 0; c < 4; c++) {
            const int j0 = (c < 2) ? (4 * a + 2 * c) : (32 + 4 * a + 2 * (c - 2));
#pragma unroll
            for (int i = 0; i < 8; i++) {
                float lo, hi;
                unpack2(acc[i][c], lo, hi);
                if (lo > bv[i]) { bv[i] = lo; bj[i] = j0; }
                if (hi > bv[i]) { bv[i] = hi; bj[i] = j0 + 1; }
            }
        }

        // ---- reduce across the 8 column-threads (first-max tie-break);
        //      every thread of the group ends with the row labels ----
#pragma unroll
        for (int off = 1; off <= 4; off <<= 1) {
#pragma unroll
            for (int i = 0; i < 8; i++) {
                float pv = __shfl_xor_sync(0xffffffffu, bv[i], off);
                int   pj = __shfl_xor_sync(0xffffffffu, bj[i], off);
                if (pv > bv[i] || (pv == bv[i] && pj < bj[i])) { bv[i] = pv; bj[i] = pj; }
            }
        }

        // ---- store own rows: per row i, thread a writes float4 q=a, q=a+8 ----
        {
            float4* og = (float4*)out + (long long)tile * (TROWS * (DIMS / 4))
                       + (g << 7);   // 8g rows * 16 float4
#pragma unroll
            for (int i = 0; i < 8; i++) {
                const int lab = bj[i];
#pragma unroll
                for (int h = 0; h < 2; h++) {
                    const int q = a + 8 * h;
                    float4 v;
                    v.x = (4 * q + 0 == lab) ? 1.0f : 0.0f;
                    v.y = (4 * q + 1 == lab) ? 1.0f : 0.0f;
                    v.z = (4 * q + 2 == lab) ? 1.0f : 0.0f;
                    v.w = (4 * q + 3 == lab) ? 1.0f : 0.0f;
                    og[(i << 4) + q] = v;
                }
            }
        }

        buf ^= 1;
    }
}

extern "C" void kernel_launch(void* const* d_in, const int* in_sizes, int n_in,
                              void* d_out, int out_size) {
    const float* x = (const float*)d_in[0];
    const float* W = (const float*)d_in[1];
    const float* b = (const float*)d_in[2];
    float* out = (float*)d_out;

    const long long rows = (long long)in_sizes[0] / DIMS;   // 2097152
    const int ntiles = (int)(rows / TROWS);                  // 8192

    int sms = 148;
    cudaDeviceGetAttribute(&sms, cudaDevAttrMultiProcessorCount, 0);

    cudaFuncSetAttribute(onehot_argmax_kernel,
                         cudaFuncAttributeMaxDynamicSharedMemorySize, SMEM_BYTES);
    onehot_argmax_kernel<<<sms, TPB, SMEM_BYTES>>>(x, W, b, out, ntiles);
}

// round 7
// speedup vs baseline: 1.0260x; 1.0260x over previous
#include <cuda_runtime.h>
#include <cstdint>

// out[i] = one_hot(argmax_j( b[j] + sum_k x[i,k]*W[k,j] ), 64)
//
// R6: persistent, 1 block/SM, TPB=512 (4 warps/SMSP), 256-row tiles,
// double-buffered cp.async x staging, one __syncthreads per tile.
// Geometry: g = t>>3 in [0,64): rows 4g..4g+3 ; a = t&7: cols
// {4a..4a+3} U {32+4a..32+4a+3}. acc = 4x8 packed f32x2 = 32 regs.
// Labels via 8-lane shuffle reduce; threads store their own rows.
// Numerics: per column b-init + ascending-k fp32 fma.rn.f32x2 chain ==
// bit-identical to all passing rounds (rel_err = 1 flipped row, zero margin).

#define DIMS 64
#define TPB 512
#define TROWS 256

// smem floats: Ws[4096] | bs[64] | xs[2][16384]
#define SMEM_FLOATS (4096 + 64 + 2 * 16384)
#define SMEM_BYTES (SMEM_FLOATS * 4)   // 147,712 B

__device__ __forceinline__ unsigned long long fma2(unsigned long long a,
                                                   unsigned long long b,
                                                   unsigned long long c) {
    unsigned long long d;
    asm("fma.rn.f32x2 %0, %1, %2, %3;" : "=l"(d) : "l"(a), "l"(b), "l"(c));
    return d;
}
__device__ __forceinline__ unsigned long long dup2(float x) {
    unsigned long long d;
    asm("mov.b64 %0, {%1, %1};" : "=l"(d) : "f"(x));
    return d;
}
__device__ __forceinline__ void unpack2(unsigned long long v, float& lo, float& hi) {
    asm("mov.b64 {%0, %1}, %2;" : "=f"(lo), "=f"(hi) : "l"(v));
}
__device__ __forceinline__ void cp16(uint32_t dst, const void* src) {
    asm volatile("cp.async.cg.shared.global [%0], [%1], 16;" :: "r"(dst), "l"(src));
}

__global__ void __launch_bounds__(TPB, 1)
onehot_argmax_kernel(const float* __restrict__ x,
                     const float* __restrict__ W,
                     const float* __restrict__ b,
                     float* __restrict__ out,
                     int ntiles) {
    extern __shared__ float smem[];
    float* Ws = smem;                 // [64][64] k-major
    float* bs = Ws + 4096;            // [64]
    float* xs = bs + 64;              // 2 x (256 rows * 64 f), swizzled

    const int t = threadIdx.x;
    const int g = t >> 3;             // row group 0..63, rows 4g..4g+3
    const int a = t & 7;              // column selector
    const int stride = gridDim.x;

    const uint32_t s_ws = (uint32_t)__cvta_generic_to_shared(Ws);
    const uint32_t s_bs = (uint32_t)__cvta_generic_to_shared(bs);
    const uint32_t s_xs = (uint32_t)__cvta_generic_to_shared(xs);

    if (blockIdx.x >= ntiles) return;

    // ---- prologue: stage W, b, and tile0 x into buffer 0 ----
    {
        const float4* W4 = (const float4*)W;
        cp16(s_ws + t * 16, W4 + t);
        cp16(s_ws + (t + TPB) * 16, W4 + t + TPB);
        if (t < 16) cp16(s_bs + t * 16, ((const float4*)b) + t);

        const float4* xg = (const float4*)x + (long long)blockIdx.x * (TROWS * (DIMS / 4));
#pragma unroll
        for (int it = 0; it < 8; it++) {
            int f = t + it * TPB;             // 0..4095
            int row = f >> 4, q = f & 15;
            int off = row * 64 + ((4 * q) ^ (row & 0x1C));
            cp16(s_xs + off * 4, xg + f);
        }
        asm volatile("cp.async.commit_group;" ::: "memory");
    }

    // all 4 rows of this thread (4g..4g+3) share one swizzle field:
    const int swb = (g & 7) << 2;     // (4g) & 0x1C
    const float* xg_base0 = xs + (g << 8);   // 4g * 64
    int buf = 0;

    for (int tile = blockIdx.x; tile < ntiles; tile += stride) {
        asm volatile("cp.async.wait_group 0;" ::: "memory");
        __syncthreads();   // buf data visible; prior compute on buf^1 finished

        // ---- prefetch next tile into buf^1 (overlaps compute below) ----
        {
            int nt = tile + stride;
            if (nt >= ntiles) nt = tile;      // harmless in-bounds duplicate
            const float4* xg = (const float4*)x + (long long)nt * (TROWS * (DIMS / 4));
            const uint32_t s_dst = s_xs + (uint32_t)(buf ^ 1) * (16384u * 4u);
#pragma unroll
            for (int it = 0; it < 8; it++) {
                int f = t + it * TPB;
                int row = f >> 4, q = f & 15;
                int off = row * 64 + ((4 * q) ^ (row & 0x1C));
                cp16(s_dst + off * 4, xg + f);
            }
            asm volatile("cp.async.commit_group;" ::: "memory");
        }

        // ---- init acc with b ----
        unsigned long long acc[4][4];
        {
            ulonglong2 b0 = *(const ulonglong2*)(bs + 4 * a);
            ulonglong2 b1 = *(const ulonglong2*)(bs + 32 + 4 * a);
#pragma unroll
            for (int i = 0; i < 4; i++) {
                acc[i][0] = b0.x; acc[i][1] = b0.y;
                acc[i][2] = b1.x; acc[i][3] = b1.y;
            }
        }

        const float* xbase = xg_base0 + buf * 16384;

        // ---- mainloop: 16 k-quads, 64 k total ----
#pragma unroll 2
        for (int kq = 0; kq < 16; kq++) {
            const int e = (4 * kq) ^ swb;
            float4 xr[4];
#pragma unroll
            for (int i = 0; i < 4; i++)
                xr[i] = *(const float4*)(xbase + (i << 6) + e);
#pragma unroll
            for (int dk = 0; dk < 4; dk++) {
                const int k = 4 * kq + dk;
                ulonglong2 w0 = *(const ulonglong2*)(Ws + (k << 6) + 4 * a);
                ulonglong2 w1 = *(const ulonglong2*)(Ws + (k << 6) + 32 + 4 * a);
#pragma unroll
                for (int i = 0; i < 4; i++) {
                    float xk = (dk == 0) ? xr[i].x : (dk == 1) ? xr[i].y
                             : (dk == 2) ? xr[i].z : xr[i].w;
                    unsigned long long x2 = dup2(xk);
                    acc[i][0] = fma2(x2, w0.x, acc[i][0]);
                    acc[i][1] = fma2(x2, w0.y, acc[i][1]);
                    acc[i][2] = fma2(x2, w1.x, acc[i][2]);
                    acc[i][3] = fma2(x2, w1.y, acc[i][3]);
                }
            }
        }

        // ---- per-thread argmax over its 8 cols (ascending j, strict >) ----
        float bv[4];
        int bj[4];
#pragma unroll
        for (int i = 0; i < 4; i++) { bv[i] = __int_as_float(0xff800000); bj[i] = 0; }
#pragma unroll
        for (int c = 0; c < 4; c++) {
            const int j0 = (c < 2) ? (4 * a + 2 * c) : (32 + 4 * a + 2 * (c - 2));
#pragma unroll
            for (int i = 0; i < 4; i++) {
                float lo, hi;
                unpack2(acc[i][c], lo, hi);
                if (lo > bv[i]) { bv[i] = lo; bj[i] = j0; }
                if (hi > bv[i]) { bv[i] = hi; bj[i] = j0 + 1; }
            }
        }

        // ---- reduce across the 8 column-threads (first-max tie-break);
        //      all 8 lanes of the group end with the 4 row labels ----
#pragma unroll
        for (int off = 1; off <= 4; off <<= 1) {
#pragma unroll
            for (int i = 0; i < 4; i++) {
                float pv = __shfl_xor_sync(0xffffffffu, bv[i], off);
                int   pj = __shfl_xor_sync(0xffffffffu, bj[i], off);
                if (pv > bv[i] || (pv == bv[i] && pj < bj[i])) { bv[i] = pv; bj[i] = pj; }
            }
        }

        // ---- store own rows: per row i, thread a writes float4 q=a, q=a+8 ----
        {
            float4* og = (float4*)out + (long long)tile * (TROWS * (DIMS / 4))
                       + (g << 6);   // 4g rows * 16 float4
#pragma unroll
            for (int i = 0; i < 4; i++) {
                const int lab = bj[i];
#pragma unroll
                for (int h = 0; h < 2; h++) {
                    const int q = a + 8 * h;
                    float4 v;
                    v.x = (4 * q + 0 == lab) ? 1.0f : 0.0f;
                    v.y = (4 * q + 1 == lab) ? 1.0f : 0.0f;
                    v.z = (4 * q + 2 == lab) ? 1.0f : 0.0f;
                    v.w = (4 * q + 3 == lab) ? 1.0f : 0.0f;
                    og[(i << 4) + q] = v;
                }
            }
        }

        buf ^= 1;
    }
}

extern "C" void kernel_launch(void* const* d_in, const int* in_sizes, int n_in,
                              void* d_out, int out_size) {
    const float* x = (const float*)d_in[0];
    const float* W = (const float*)d_in[1];
    const float* b = (const float*)d_in[2];
    float* out = (float*)d_out;

    const long long rows = (long long)in_sizes[0] / DIMS;   // 2097152
    const int ntiles = (int)(rows / TROWS);                  // 8192

    int sms = 148;
    cudaDeviceGetAttribute(&sms, cudaDevAttrMultiProcessorCount, 0);

    cudaFuncSetAttribute(onehot_argmax_kernel,
                         cudaFuncAttributeMaxDynamicSharedMemorySize, SMEM_BYTES);
    onehot_argmax_kernel<<<sms, TPB, SMEM_BYTES>>>(x, W, b, out, ntiles);
}

// round 8
// speedup vs baseline: 1.1090x; 1.0808x over previous
#include <cuda_runtime.h>
#include <cstdint>

// out[i] = one_hot(argmax_j( b[j] + sum_k x[i,k]*W[k,j] ), 64)
//
// R8: persistent, 1 block/SM, TPB=384 = 3 INDEPENDENT groups of 128 threads.
// Each group (1 warp/SMSP) streams 128-row tiles with its own double-buffered
// cp.async pipeline and its own named barrier; groups never block-sync after
// the prologue, so one group's staging/epilogue overlaps the others' FMA.
// Geometry per group (proven R3 mainloop, LDS-wf/FFMA2 = 0.125):
//   g = (t&127)>>3 in [0,16): rows 8g..8g+7 ; a = t&7: cols
//   {4a..4a+3} U {32+4a..32+4a+3}. acc = 8x8 packed f32x2 = 64 regs.
// Numerics: per column b-init + ascending-k fp32 fma.rn.f32x2 chain ==
// bit-identical to all passing rounds (rel_err = 1 flipped row, zero margin).

#define DIMS 64
#define TPB 384
#define GSZ 128            // threads per group
#define TROWS 128          // rows per tile
#define TILE_F4 (TROWS * DIMS / 4)    // 2048 float4 per tile
#define TILE_FLOATS (TROWS * DIMS)    // 8192 floats

// smem floats: Ws[4096] | bs[64] | xs[6][8192]
#define SMEM_FLOATS (4096 + 64 + 6 * TILE_FLOATS)
#define SMEM_BYTES (SMEM_FLOATS * 4)   // 213,248 B

__device__ __forceinline__ unsigned long long fma2(unsigned long long a,
                                                   unsigned long long b,
                                                   unsigned long long c) {
    unsigned long long d;
    asm("fma.rn.f32x2 %0, %1, %2, %3;" : "=l"(d) : "l"(a), "l"(b), "l"(c));
    return d;
}
__device__ __forceinline__ unsigned long long dup2(float x) {
    unsigned long long d;
    asm("mov.b64 %0, {%1, %1};" : "=l"(d) : "f"(x));
    return d;
}
__device__ __forceinline__ void unpack2(unsigned long long v, float& lo, float& hi) {
    asm("mov.b64 {%0, %1}, %2;" : "=f"(lo), "=f"(hi) : "l"(v));
}
__device__ __forceinline__ void cp16(uint32_t dst, const void* src) {
    asm volatile("cp.async.cg.shared.global [%0], [%1], 16;" :: "r"(dst), "l"(src));
}
__device__ __forceinline__ void gbar(int id) {
    asm volatile("bar.sync %0, %1;" :: "r"(id), "r"(GSZ) : "memory");
}

__global__ void __launch_bounds__(TPB, 1)
onehot_argmax_kernel(const float* __restrict__ x,
                     const float* __restrict__ W,
                     const float* __restrict__ b,
                     float* __restrict__ out,
                     int ntiles) {
    extern __shared__ float smem[];
    float* Ws = smem;                 // [64][64] k-major
    float* bs = Ws + 4096;            // [64]
    float* xs = bs + 64;              // 6 x 8192 floats, swizzled tiles

    const int t  = threadIdx.x;
    const int p  = t / GSZ;           // group 0..2
    const int tl = t & (GSZ - 1);     // index within group
    const int g  = tl >> 3;           // row group 0..15, rows 8g..8g+7
    const int a  = tl & 7;            // column selector
    const int nstreams = 3 * gridDim.x;
    const int s0 = blockIdx.x * 3 + p;    // this group's stream id

    const uint32_t s_ws = (uint32_t)__cvta_generic_to_shared(Ws);
    const uint32_t s_bs = (uint32_t)__cvta_generic_to_shared(bs);
    const uint32_t s_xs = (uint32_t)__cvta_generic_to_shared(xs);

    // ---- prologue: whole block stages W+b; each group stages its tile0 ----
    {
        const float4* W4 = (const float4*)W;
        for (int i = t; i < 1024; i += TPB) cp16(s_ws + i * 16, W4 + i);
        if (t < 16) cp16(s_bs + t * 16, ((const float4*)b) + t);

        if (s0 < ntiles) {
            const float4* xg = (const float4*)x + (long long)s0 * TILE_F4;
            const uint32_t s_dst = s_xs + (uint32_t)(p * 2) * (TILE_FLOATS * 4u);
#pragma unroll
            for (int it = 0; it < 16; it++) {
                int f = tl + it * GSZ;            // 0..2047
                int row = f >> 4, q = f & 15;
                int off = row * 64 + ((4 * q) ^ (row & 0x1C));
                cp16(s_dst + off * 4, xg + f);
            }
        }
        asm volatile("cp.async.commit_group;" ::: "memory");
    }
    __syncthreads();   // W/b visible to everyone; groups diverge from here

    const int swb = (g & 3) << 3;
    int buf = 0;

    for (int tile = s0; tile < ntiles; tile += nstreams) {
        asm volatile("cp.async.wait_group 0;" ::: "memory");
        gbar(1 + p);   // buf data visible to whole group; prior reads done

        // ---- prefetch next tile into buf^1 (overlaps compute below) ----
        {
            int nt = tile + nstreams;
            if (nt >= ntiles) nt = tile;          // harmless duplicate
            const float4* xg = (const float4*)x + (long long)nt * TILE_F4;
            const uint32_t s_dst = s_xs +
                (uint32_t)(p * 2 + (buf ^ 1)) * (TILE_FLOATS * 4u);
#pragma unroll
            for (int it = 0; it < 16; it++) {
                int f = tl + it * GSZ;
                int row = f >> 4, q = f & 15;
                int off = row * 64 + ((4 * q) ^ (row & 0x1C));
                cp16(s_dst + off * 4, xg + f);
            }
            asm volatile("cp.async.commit_group;" ::: "memory");
        }

        // ---- init acc with b ----
        unsigned long long acc[8][4];
        {
            ulonglong2 b0 = *(const ulonglong2*)(bs + 4 * a);
            ulonglong2 b1 = *(const ulonglong2*)(bs + 32 + 4 * a);
#pragma unroll
            for (int i = 0; i < 8; i++) {
                acc[i][0] = b0.x; acc[i][1] = b0.y;
                acc[i][2] = b1.x; acc[i][3] = b1.y;
            }
        }

        const float* xbase = xs + (p * 2 + buf) * TILE_FLOATS + (g << 9);

        // ---- mainloop: 16 k-quads, 64 k total ----
#pragma unroll 2
        for (int kq = 0; kq < 16; kq++) {
            const int e0 = (4 * kq) ^ swb;
            const int e4 = (4 * kq) ^ (swb + 4);
            float4 xr[8];
#pragma unroll
            for (int i = 0; i < 8; i++)
                xr[i] = *(const float4*)(xbase + (i << 6) + ((i & 4) ? e4 : e0));
#pragma unroll
            for (int dk = 0; dk < 4; dk++) {
                const int k = 4 * kq + dk;
                ulonglong2 w0 = *(const ulonglong2*)(Ws + (k << 6) + 4 * a);
                ulonglong2 w1 = *(const ulonglong2*)(Ws + (k << 6) + 32 + 4 * a);
#pragma unroll
                for (int i = 0; i < 8; i++) {
                    float xk = (dk == 0) ? xr[i].x : (dk == 1) ? xr[i].y
                             : (dk == 2) ? xr[i].z : xr[i].w;
                    unsigned long long x2 = dup2(xk);
                    acc[i][0] = fma2(x2, w0.x, acc[i][0]);
                    acc[i][1] = fma2(x2, w0.y, acc[i][1]);
                    acc[i][2] = fma2(x2, w1.x, acc[i][2]);
                    acc[i][3] = fma2(x2, w1.y, acc[i][3]);
                }
            }
        }

        // ---- per-thread argmax over its 8 cols (ascending j, strict >) ----
        float bv[8];
        int bj[8];
#pragma unroll
        for (int i = 0; i < 8; i++) { bv[i] = __int_as_float(0xff800000); bj[i] = 0; }
#pragma unroll
        for (int c = 0; c < 4; c++) {
            const int j0 = (c < 2) ? (4 * a + 2 * c) : (32 + 4 * a + 2 * (c - 2));
#pragma unroll
            for (int i = 0; i < 8; i++) {
                float lo, hi;
                unpack2(acc[i][c], lo, hi);
                if (lo > bv[i]) { bv[i] = lo; bj[i] = j0; }
                if (hi > bv[i]) { bv[i] = hi; bj[i] = j0 + 1; }
            }
        }

        // ---- reduce across the 8 column-lanes (first-max tie-break) ----
#pragma unroll
        for (int off = 1; off <= 4; off <<= 1) {
#pragma unroll
            for (int i = 0; i < 8; i++) {
                float pv = __shfl_xor_sync(0xffffffffu, bv[i], off);
                int   pj = __shfl_xor_sync(0xffffffffu, bj[i], off);
                if (pv > bv[i] || (pv == bv[i] && pj < bj[i])) { bv[i] = pv; bj[i] = pj; }
            }
        }

        // ---- store own rows: per row i, lane a writes float4 q=a, q=a+8 ----
        {
            float4* og = (float4*)out + (long long)tile * TILE_F4 + (g << 7);
#pragma unroll
            for (int i = 0; i < 8; i++) {
                const int lab = bj[i];
#pragma unroll
                for (int h = 0; h < 2; h++) {
                    const int q = a + 8 * h;
                    float4 v;
                    v.x = (4 * q + 0 == lab) ? 1.0f : 0.0f;
                    v.y = (4 * q + 1 == lab) ? 1.0f : 0.0f;
                    v.z = (4 * q + 2 == lab) ? 1.0f : 0.0f;
                    v.w = (4 * q + 3 == lab) ? 1.0f : 0.0f;
                    og[(i << 4) + q] = v;
                }
            }
        }

        buf ^= 1;
    }
}

extern "C" void kernel_launch(void* const* d_in, const int* in_sizes, int n_in,
                              void* d_out, int out_size) {
    const float* x = (const float*)d_in[0];
    const float* W = (const float*)d_in[1];
    const float* b = (const float*)d_in[2];
    float* out = (float*)d_out;

    const long long rows = (long long)in_sizes[0] / DIMS;   // 2097152
    const int ntiles = (int)(rows / TROWS);                  // 16384

    int sms = 148;
    cudaDeviceGetAttribute(&sms, cudaDevAttrMultiProcessorCount, 0);

    cudaFuncSetAttribute(onehot_argmax_kernel,
                         cudaFuncAttributeMaxDynamicSharedMemorySize, SMEM_BYTES);
    onehot_argmax_kernel<<<sms, TPB, SMEM_BYTES>>>(x, W, b, out, ntiles);
}

// round 9
// speedup vs baseline: 1.1093x; 1.0003x over previous
#include <cuda_runtime.h>
#include <cstdint>

// out[i] = one_hot(argmax_j( b[j] + sum_k x[i,k]*W[k,j] ), 64)
//
// R9 = R8 (358us) + phase skew. R8: persistent, 1 block/SM, TPB=384 =
// 3 independent 128-thread groups, each streaming 128-row tiles with its own
// double-buffered cp.async pipeline + named barrier. R8's flaw: equal periods
// + synced start => groups phase-lock, all 3 warps/SMSP hit the (no-FMA)
// epilogue together => FMA pipe idles ~1/3 of the time (fma=68%).
// Fix: group p spins p*6000 cycles once after the prologue, de-phasing the
// pipelines so epilogues interleave and the FMA pipe stays fed.
// Mainloop/numerics byte-identical to R8: per column b-init + ascending-k
// fp32 fma.rn.f32x2 chain (rel_err = 1 flipped row, zero margin).

#define DIMS 64
#define TPB 384
#define GSZ 128            // threads per group
#define TROWS 128          // rows per tile
#define TILE_F4 (TROWS * DIMS / 4)    // 2048 float4 per tile
#define TILE_FLOATS (TROWS * DIMS)    // 8192 floats
#define SKEW_CYCLES 6000ull

// smem floats: Ws[4096] | bs[64] | xs[6][8192]
#define SMEM_FLOATS (4096 + 64 + 6 * TILE_FLOATS)
#define SMEM_BYTES (SMEM_FLOATS * 4)   // 213,248 B

__device__ __forceinline__ unsigned long long fma2(unsigned long long a,
                                                   unsigned long long b,
                                                   unsigned long long c) {
    unsigned long long d;
    asm("fma.rn.f32x2 %0, %1, %2, %3;" : "=l"(d) : "l"(a), "l"(b), "l"(c));
    return d;
}
__device__ __forceinline__ unsigned long long dup2(float x) {
    unsigned long long d;
    asm("mov.b64 %0, {%1, %1};" : "=l"(d) : "f"(x));
    return d;
}
__device__ __forceinline__ void unpack2(unsigned long long v, float& lo, float& hi) {
    asm("mov.b64 {%0, %1}, %2;" : "=f"(lo), "=f"(hi) : "l"(v));
}
__device__ __forceinline__ void cp16(uint32_t dst, const void* src) {
    asm volatile("cp.async.cg.shared.global [%0], [%1], 16;" :: "r"(dst), "l"(src));
}
__device__ __forceinline__ void gbar(int id) {
    asm volatile("bar.sync %0, %1;" :: "r"(id), "r"(GSZ) : "memory");
}

__global__ void __launch_bounds__(TPB, 1)
onehot_argmax_kernel(const float* __restrict__ x,
                     const float* __restrict__ W,
                     const float* __restrict__ b,
                     float* __restrict__ out,
                     int ntiles) {
    extern __shared__ float smem[];
    float* Ws = smem;                 // [64][64] k-major
    float* bs = Ws + 4096;            // [64]
    float* xs = bs + 64;              // 6 x 8192 floats, swizzled tiles

    const int t  = threadIdx.x;
    const int p  = t / GSZ;           // group 0..2
    const int tl = t & (GSZ - 1);     // index within group
    const int g  = tl >> 3;           // row group 0..15, rows 8g..8g+7
    const int a  = tl & 7;            // column selector
    const int nstreams = 3 * gridDim.x;
    const int s0 = blockIdx.x * 3 + p;    // this group's stream id

    const uint32_t s_ws = (uint32_t)__cvta_generic_to_shared(Ws);
    const uint32_t s_bs = (uint32_t)__cvta_generic_to_shared(bs);
    const uint32_t s_xs = (uint32_t)__cvta_generic_to_shared(xs);

    // ---- prologue: whole block stages W+b; each group stages its tile0 ----
    {
        const float4* W4 = (const float4*)W;
        for (int i = t; i < 1024; i += TPB) cp16(s_ws + i * 16, W4 + i);
        if (t < 16) cp16(s_bs + t * 16, ((const float4*)b) + t);

        if (s0 < ntiles) {
            const float4* xg = (const float4*)x + (long long)s0 * TILE_F4;
            const uint32_t s_dst = s_xs + (uint32_t)(p * 2) * (TILE_FLOATS * 4u);
#pragma unroll
            for (int it = 0; it < 16; it++) {
                int f = tl + it * GSZ;            // 0..2047
                int row = f >> 4, q = f & 15;
                int off = row * 64 + ((4 * q) ^ (row & 0x1C));
                cp16(s_dst + off * 4, xg + f);
            }
        }
        asm volatile("cp.async.commit_group;" ::: "memory");
    }
    __syncthreads();   // W/b visible to everyone; groups diverge from here

    // ---- phase skew: de-phase the 3 groups so their epilogues interleave ----
    if (p != 0) {
        const unsigned long long tgt = (unsigned long long)p * SKEW_CYCLES;
        const unsigned long long t0 = clock64();
        while (clock64() - t0 < tgt) { }
    }

    const int swb = (g & 3) << 3;
    int buf = 0;

    for (int tile = s0; tile < ntiles; tile += nstreams) {
        asm volatile("cp.async.wait_group 0;" ::: "memory");
        gbar(1 + p);   // buf data visible to whole group; prior reads done

        // ---- prefetch next tile into buf^1 (overlaps compute below) ----
        {
            int nt = tile + nstreams;
            if (nt >= ntiles) nt = tile;          // harmless duplicate
            const float4* xg = (const float4*)x + (long long)nt * TILE_F4;
            const uint32_t s_dst = s_xs +
                (uint32_t)(p * 2 + (buf ^ 1)) * (TILE_FLOATS * 4u);
#pragma unroll
            for (int it = 0; it < 16; it++) {
                int f = tl + it * GSZ;
                int row = f >> 4, q = f & 15;
                int off = row * 64 + ((4 * q) ^ (row & 0x1C));
                cp16(s_dst + off * 4, xg + f);
            }
            asm volatile("cp.async.commit_group;" ::: "memory");
        }

        // ---- init acc with b ----
        unsigned long long acc[8][4];
        {
            ulonglong2 b0 = *(const ulonglong2*)(bs + 4 * a);
            ulonglong2 b1 = *(const ulonglong2*)(bs + 32 + 4 * a);
#pragma unroll
            for (int i = 0; i < 8; i++) {
                acc[i][0] = b0.x; acc[i][1] = b0.y;
                acc[i][2] = b1.x; acc[i][3] = b1.y;
            }
        }

        const float* xbase = xs + (p * 2 + buf) * TILE_FLOATS + (g << 9);

        // ---- mainloop: 16 k-quads, 64 k total ----
#pragma unroll 2
        for (int kq = 0; kq < 16; kq++) {
            const int e0 = (4 * kq) ^ swb;
            const int e4 = (4 * kq) ^ (swb + 4);
            float4 xr[8];
#pragma unroll
            for (int i = 0; i < 8; i++)
                xr[i] = *(const float4*)(xbase + (i << 6) + ((i & 4) ? e4 : e0));
#pragma unroll
            for (int dk = 0; dk < 4; dk++) {
                const int k = 4 * kq + dk;
                ulonglong2 w0 = *(const ulonglong2*)(Ws + (k << 6) + 4 * a);
                ulonglong2 w1 = *(const ulonglong2*)(Ws + (k << 6) + 32 + 4 * a);
#pragma unroll
                for (int i = 0; i < 8; i++) {
                    float xk = (dk == 0) ? xr[i].x : (dk == 1) ? xr[i].y
                             : (dk == 2) ? xr[i].z : xr[i].w;
                    unsigned long long x2 = dup2(xk);
                    acc[i][0] = fma2(x2, w0.x, acc[i][0]);
                    acc[i][1] = fma2(x2, w0.y, acc[i][1]);
                    acc[i][2] = fma2(x2, w1.x, acc[i][2]);
                    acc[i][3] = fma2(x2, w1.y, acc[i][3]);
                }
            }
        }

        // ---- per-thread argmax over its 8 cols (ascending j, strict >) ----
        float bv[8];
        int bj[8];
#pragma unroll
        for (int i = 0; i < 8; i++) { bv[i] = __int_as_float(0xff800000); bj[i] = 0; }
#pragma unroll
        for (int c = 0; c < 4; c++) {
            const int j0 = (c < 2) ? (4 * a + 2 * c) : (32 + 4 * a + 2 * (c - 2));
#pragma unroll
            for (int i = 0; i < 8; i++) {
                float lo, hi;
                unpack2(acc[i][c], lo, hi);
                if (lo > bv[i]) { bv[i] = lo; bj[i] = j0; }
                if (hi > bv[i]) { bv[i] = hi; bj[i] = j0 + 1; }
            }
        }

        // ---- reduce across the 8 column-lanes (first-max tie-break) ----
#pragma unroll
        for (int off = 1; off <= 4; off <<= 1) {
#pragma unroll
            for (int i = 0; i < 8; i++) {
                float pv = __shfl_xor_sync(0xffffffffu, bv[i], off);
                int   pj = __shfl_xor_sync(0xffffffffu, bj[i], off);
                if (pv > bv[i] || (pv == bv[i] && pj < bj[i])) { bv[i] = pv; bj[i] = pj; }
            }
        }

        // ---- store own rows: per row i, lane a writes float4 q=a, q=a+8 ----
        {
            float4* og = (float4*)out + (long long)tile * TILE_F4 + (g << 7);
#pragma unroll
            for (int i = 0; i < 8; i++) {
                const int lab = bj[i];
#pragma unroll
                for (int h = 0; h < 2; h++) {
                    const int q = a + 8 * h;
                    float4 v;
                    v.x = (4 * q + 0 == lab) ? 1.0f : 0.0f;
                    v.y = (4 * q + 1 == lab) ? 1.0f : 0.0f;
                    v.z = (4 * q + 2 == lab) ? 1.0f : 0.0f;
                    v.w = (4 * q + 3 == lab) ? 1.0f : 0.0f;
                    og[(i << 4) + q] = v;
                }
            }
        }

        buf ^= 1;
    }
}

extern "C" void kernel_launch(void* const* d_in, const int* in_sizes, int n_in,
                              void* d_out, int out_size) {
    const float* x = (const float*)d_in[0];
    const float* W = (const float*)d_in[1];
    const float* b = (const float*)d_in[2];
    float* out = (float*)d_out;

    const long long rows = (long long)in_sizes[0] / DIMS;   // 2097152
    const int ntiles = (int)(rows / TROWS);                  // 16384

    int sms = 148;
    cudaDeviceGetAttribute(&sms, cudaDevAttrMultiProcessorCount, 0);

    cudaFuncSetAttribute(onehot_argmax_kernel,
                         cudaFuncAttributeMaxDynamicSharedMemorySize, SMEM_BYTES);
    onehot_argmax_kernel<<<sms, TPB, SMEM_BYTES>>>(x, W, b, out, ntiles);
}